// round 1
// baseline (speedup 1.0000x reference)
#include <cuda_runtime.h>
#include <stdint.h>

// ---------------------------------------------------------------------------
// BatchTopK activation: global top-(32*num_tokens) over masked [B,S,F] tensor,
// scatter relu'd winners into zeros, EMA threshold update.
//
// Pipeline:
//   K0: zero persistent device-global state (graph-replay safe)
//   K1: 4096-bin histogram of key top-12 bits (masked tokens skipped)
//   K2: suffix-scan histogram -> boundary bin b1 + 'need' inside it
//   K3: write full output (relu for bins > b1, zeros elsewhere),
//       compact boundary-bin candidates (key, idx)
//   K4: exact radix select among candidates, scatter, ties by lowest index,
//       threshold = 0.99*thr + 0.01*v_k  (v_k = k-th largest, when > 0)
// ---------------------------------------------------------------------------

#define NBIN 4096
#define CAP (1u << 22)      // candidate capacity (32 MB static buffer)
#define MAXTIE 4096

__device__ unsigned int g_hist[NBIN];
__device__ int g_b1;
__device__ unsigned int g_need;
__device__ unsigned int g_ncand;
__device__ uint2 g_cand[CAP];   // (key, flat index)

// Order-preserving float->uint key: larger key <=> larger float.
__device__ __forceinline__ unsigned int f2key(unsigned int u) {
    unsigned int m = ((unsigned int)((int)u >> 31)) | 0x80000000u;
    return u ^ m;
}
__device__ __forceinline__ float key2f(unsigned int k) {
    unsigned int u = (k & 0x80000000u) ? (k ^ 0x80000000u) : ~k;
    return __uint_as_float(u);
}

// ---------------------------------------------------------------- K0: init
__global__ void k0_init() {
    int tid = blockIdx.x * blockDim.x + threadIdx.x;
    for (int b = tid; b < NBIN; b += blockDim.x * gridDim.x) g_hist[b] = 0u;
    if (tid == 0) { g_b1 = -1; g_need = 0u; g_ncand = 0u; }
}

// ------------------------------------------------------------ K1: histogram
__global__ void k1_hist(const float* __restrict__ x,
                        const int* __restrict__ mask, int T, int F) {
    __shared__ unsigned int sh[NBIN];
    for (int b = threadIdx.x; b < NBIN; b += blockDim.x) sh[b] = 0u;
    __syncthreads();

    const int f4 = F >> 2;
    for (int t = blockIdx.x; t < T; t += gridDim.x) {
        if (mask[t] == 0) continue;               // whole masked token skipped
        const float4* xt = (const float4*)(x + (size_t)t * F);
        for (int i = threadIdx.x; i < f4; i += blockDim.x) {
            float4 v = __ldg(&xt[i]);
            atomicAdd(&sh[f2key(__float_as_uint(v.x)) >> 20], 1u);
            atomicAdd(&sh[f2key(__float_as_uint(v.y)) >> 20], 1u);
            atomicAdd(&sh[f2key(__float_as_uint(v.z)) >> 20], 1u);
            atomicAdd(&sh[f2key(__float_as_uint(v.w)) >> 20], 1u);
        }
    }
    __syncthreads();
    for (int b = threadIdx.x; b < NBIN; b += blockDim.x) {
        unsigned int v = sh[b];
        if (v) atomicAdd(&g_hist[b], v);
    }
}

// ------------------------------------------------- K2: find boundary bin
// 1024 threads, 4 bins each. Suffix-sum from the top of the key space.
__global__ void k2_findbin(unsigned int ktot) {
    __shared__ unsigned int part[1024];
    const int tid = threadIdx.x;

    unsigned int h[4];
    unsigned int own = 0u;
#pragma unroll
    for (int j = 0; j < 4; j++) { h[j] = g_hist[tid * 4 + j]; own += h[j]; }
    part[tid] = own;
    __syncthreads();

    // inclusive suffix scan (Hillis-Steele)
    for (int off = 1; off < 1024; off <<= 1) {
        unsigned int v = (tid + off < 1024) ? part[tid + off] : 0u;
        __syncthreads();
        part[tid] += v;
        __syncthreads();
    }
    unsigned int above = part[tid] - own;  // count in bins strictly above chunk

    unsigned int cum = above;
    for (int j = 3; j >= 0; j--) {
        cum += h[j];
        if (cum >= ktot && (cum - h[j]) < ktot) {
            g_b1 = tid * 4 + j;
            g_need = ktot - (cum - h[j]);
        }
    }
    // If total eligible < ktot no thread fires: g_b1 stays -1 (select all).
}

// --------------------------------------------- K3: write output + compact
__global__ void k3_out(const float* __restrict__ x,
                       const int* __restrict__ mask,
                       float* __restrict__ out, int T, int F) {
    const int b1 = g_b1;
    const int f4 = F >> 2;
    for (int t = blockIdx.x; t < T; t += gridDim.x) {
        float4* ot = (float4*)(out + (size_t)t * F);
        if (mask[t] == 0) {
            const float4 z = make_float4(0.f, 0.f, 0.f, 0.f);
            for (int i = threadIdx.x; i < f4; i += blockDim.x) ot[i] = z;
            continue;
        }
        const float4* xt = (const float4*)(x + (size_t)t * F);
        const int tbase = t * F;
        for (int i = threadIdx.x; i < f4; i += blockDim.x) {
            float4 v = __ldg(&xt[i]);
            const int gb = tbase + (i << 2);
            float4 r;
            {
                unsigned int key = f2key(__float_as_uint(v.x));
                int bin = (int)(key >> 20);
                r.x = (bin > b1) ? fmaxf(v.x, 0.f) : 0.f;
                if (bin == b1) {
                    unsigned int p = atomicAdd(&g_ncand, 1u);
                    if (p < CAP) g_cand[p] = make_uint2(key, (unsigned int)(gb + 0));
                }
            }
            {
                unsigned int key = f2key(__float_as_uint(v.y));
                int bin = (int)(key >> 20);
                r.y = (bin > b1) ? fmaxf(v.y, 0.f) : 0.f;
                if (bin == b1) {
                    unsigned int p = atomicAdd(&g_ncand, 1u);
                    if (p < CAP) g_cand[p] = make_uint2(key, (unsigned int)(gb + 1));
                }
            }
            {
                unsigned int key = f2key(__float_as_uint(v.z));
                int bin = (int)(key >> 20);
                r.z = (bin > b1) ? fmaxf(v.z, 0.f) : 0.f;
                if (bin == b1) {
                    unsigned int p = atomicAdd(&g_ncand, 1u);
                    if (p < CAP) g_cand[p] = make_uint2(key, (unsigned int)(gb + 2));
                }
            }
            {
                unsigned int key = f2key(__float_as_uint(v.w));
                int bin = (int)(key >> 20);
                r.w = (bin > b1) ? fmaxf(v.w, 0.f) : 0.f;
                if (bin == b1) {
                    unsigned int p = atomicAdd(&g_ncand, 1u);
                    if (p < CAP) g_cand[p] = make_uint2(key, (unsigned int)(gb + 3));
                }
            }
            ot[i] = r;
        }
    }
}

// ------------------------------- K4: exact select among candidates + scatter
__global__ void k4_select(const float* __restrict__ thr_in,
                          float* __restrict__ out, int n, int out_size) {
    __shared__ unsigned int h2[256];
    __shared__ unsigned int s_sel, s_need, s_tiecnt;
    __shared__ unsigned int tie_idx[MAXTIE];

    const int tid = threadIdx.x;
    const int bd = blockDim.x;
    const int b1 = g_b1;
    const unsigned int nc = min(g_ncand, CAP);
    unsigned int need = g_need;
    unsigned int ck = 0u;
    bool have_cut = false;

    if (b1 >= 0 && need > 0u && nc > 0u) {
        have_cut = true;
        unsigned int bmask = 0xFFF00000u;
        unsigned int bval = ((unsigned int)b1) << 20;

        const int shifts[3] = {12, 4, 0};
        const unsigned int widths[3] = {256u, 256u, 16u};
#pragma unroll
        for (int lev = 0; lev < 3; lev++) {
            const int sh = shifts[lev];
            const unsigned int w = widths[lev];
            for (unsigned int d = tid; d < w; d += bd) h2[d] = 0u;
            __syncthreads();
            for (unsigned int i = tid; i < nc; i += bd) {
                unsigned int key = g_cand[i].x;
                if ((key & bmask) == bval)
                    atomicAdd(&h2[(key >> sh) & (w - 1u)], 1u);
            }
            __syncthreads();
            if (tid == 0) {
                unsigned int cum = 0u;
                s_sel = 0u; s_need = need;   // safety defaults
                for (int d = (int)w - 1; d >= 0; d--) {
                    cum += h2[d];
                    if (cum >= need) {
                        s_sel = (unsigned int)d;
                        s_need = need - (cum - h2[d]);
                        break;
                    }
                }
            }
            __syncthreads();
            bval |= s_sel << sh;
            bmask |= (w - 1u) << sh;
            need = s_need;
            __syncthreads();
        }
        ck = bval;

        // scatter strict winners; collect ties
        if (tid == 0) s_tiecnt = 0u;
        __syncthreads();
        for (unsigned int i = tid; i < nc; i += bd) {
            uint2 c = g_cand[i];
            if (c.x > ck) {
                out[c.y] = fmaxf(key2f(c.x), 0.f);
            } else if (c.x == ck) {
                unsigned int p = atomicAdd(&s_tiecnt, 1u);
                if (p < MAXTIE) tie_idx[p] = c.y;
            }
        }
        __syncthreads();
        const unsigned int tcnt = s_tiecnt;
        const float cv = fmaxf(key2f(ck), 0.f);
        if (tcnt <= (unsigned int)MAXTIE) {
            // ties resolved by lowest flat index (matches sorted top_k order)
            for (unsigned int i = tid; i < tcnt; i += bd) {
                unsigned int mi = tie_idx[i];
                unsigned int rank = 0u;
                for (unsigned int j = 0; j < tcnt; j++)
                    rank += (tie_idx[j] < mi) ? 1u : 0u;
                if (rank < need) out[mi] = cv;
            }
        } else {
            // pathological tie flood: take first 'need' recorded
            for (unsigned int i = tid; i < need && i < (unsigned int)MAXTIE; i += bd)
                out[tie_idx[i]] = cv;
        }
    }

    if (tid == 0 && out_size > n) {
        float thr = thr_in[0];
        float res = thr;
        if (have_cut) {
            float vk = key2f(ck);   // k-th largest value = min selected
            if (vk > 0.f) res = 0.99f * thr + 0.01f * vk;
        }
        out[out_size - 1] = res;
    }
}

// ---------------------------------------------------------------------------
extern "C" void kernel_launch(void* const* d_in, const int* in_sizes, int n_in,
                              void* d_out, int out_size) {
    const float* x = (const float*)d_in[0];
    const int* mask = (const int*)d_in[1];
    const float* thr = (const float*)d_in[2];
    float* out = (float*)d_out;

    const int n = in_sizes[0];      // B*S*F
    const int T = in_sizes[1];      // B*S tokens
    const int F = n / T;            // features per token (divisible by 4)
    const unsigned int ktot = 32u * (unsigned int)T;

    int g1 = T < 512 ? T : 512;
    int g3 = T < 2048 ? T : 2048;

    k0_init<<<1, 256>>>();
    k1_hist<<<g1, 256>>>(x, mask, T, F);
    k2_findbin<<<1, 1024>>>(ktot);
    k3_out<<<g3, 256>>>(x, mask, out, T, F);
    k4_select<<<1, 1024>>>(thr, out, n, out_size);
}

// round 2
// speedup vs baseline: 1.1838x; 1.1838x over previous
#include <cuda_runtime.h>
#include <stdint.h>

// ---------------------------------------------------------------------------
// BatchTopK: global top-(32*T) over masked [B,S,F], scatter relu'd winners,
// EMA threshold. Single-read pipeline:
//   K0  : zero persistent state
//   KM  : fused pass — zero full output, read eligible x ONCE, compact all
//         above-pivot (key,idx) via per-block smem staging, hist top-12 bits
//   K2  : suffix-scan hist -> boundary bin b1 + need (or set fallback flag)
//   FB1/FB2/FB3: exactness fallback (early-exit when flag==0)
//   K4a : split candidates: bin>b1 -> scatter winners; bin==b1 -> cand2 + h2
//   K4b : finish radix select in bin b1, scatter boundary winners + ties,
//         write EMA threshold
// ---------------------------------------------------------------------------

#define NBIN 4096
#define PIVOT_BIN 3072
#define PIVOT_KEY 0xC0000000u   // f2key(2.0f): candidates are x >= 2.0
#define KEY_ZERO  0x80000000u   // f2key(+0.0f)
#define CAP  (1u << 22)
#define CAP2 (1u << 20)
#define MAXTIE 4096

__device__ unsigned g_hist[NBIN];
__device__ unsigned g_histF[NBIN];
__device__ unsigned g_h2[256];
__device__ int      g_b1;
__device__ unsigned g_need;
__device__ unsigned g_ncand;
__device__ unsigned g_ncand2;
__device__ unsigned g_flag;
__device__ unsigned g_minpos;
__device__ uint2    g_cand[CAP];
__device__ uint2    g_cand2[CAP2];

__device__ __forceinline__ unsigned f2key(unsigned u) {
    unsigned m = ((unsigned)((int)u >> 31)) | 0x80000000u;
    return u ^ m;
}
__device__ __forceinline__ float key2f(unsigned k) {
    unsigned u = (k & 0x80000000u) ? (k ^ 0x80000000u) : ~k;
    return __uint_as_float(u);
}

// ---------------------------------------------------------------- K0: init
__global__ void k0_init() {
    int tid = blockIdx.x * blockDim.x + threadIdx.x;
    int nt = blockDim.x * gridDim.x;
    for (int i = tid; i < NBIN; i += nt) { g_hist[i] = 0u; g_histF[i] = 0u; }
    for (int i = tid; i < 256; i += nt) g_h2[i] = 0u;
    if (tid == 0) {
        g_b1 = -1; g_need = 0u; g_ncand = 0u; g_ncand2 = 0u;
        g_flag = 0u; g_minpos = 0xFFFFFFFFu;
    }
}

// ----------------------------------------------------- KM: fused main pass
// blockDim MUST be 256 (smem staging buffer sized for 4*256*4 = 4096 elems).
__global__ void km_fused(const float* __restrict__ x,
                         const int* __restrict__ mask,
                         float* __restrict__ out, int T, int F) {
    __shared__ unsigned shist[1024];          // bins PIVOT_BIN..4095
    __shared__ uint2 sbuf[4096];
    __shared__ unsigned scnt, sbase;
    const int tid = threadIdx.x;
    const int bd = blockDim.x;
    const int f4 = F >> 2;
    for (int i = tid; i < 1024; i += bd) shist[i] = 0u;
    __syncthreads();

    const float4 z4 = make_float4(0.f, 0.f, 0.f, 0.f);
    const int chunk = 4 * bd;                         // float4s per chunk
    const int nchunk = (f4 + chunk - 1) / chunk;

    for (int t = blockIdx.x; t < T; t += gridDim.x) {
        float4* ot = (float4*)(out + (size_t)t * F);
        if (mask[t] == 0) {                           // masked: zeros only
            for (int i = tid; i < f4; i += bd) ot[i] = z4;
            continue;
        }
        const float4* xt = (const float4*)(x + (size_t)t * F);
        const unsigned tbase = (unsigned)t * (unsigned)F;

        for (int c = 0; c < nchunk; c++) {
            if (tid == 0) scnt = 0u;
            __syncthreads();
            const int base = c * chunk;
            float4 v[4]; int ii[4]; bool act[4];
#pragma unroll
            for (int j = 0; j < 4; j++) {             // 4 independent loads (MLP)
                ii[j] = base + j * bd + tid;
                act[j] = ii[j] < f4;
                v[j] = act[j] ? xt[ii[j]] : z4;
            }
#pragma unroll
            for (int j = 0; j < 4; j++) {
                if (act[j]) {
                    const unsigned gb = tbase + ((unsigned)ii[j] << 2);
                    const float* vp = (const float*)&v[j];
#pragma unroll
                    for (int e = 0; e < 4; e++) {
                        unsigned key = f2key(__float_as_uint(vp[e]));
                        if (key >= PIVOT_KEY) {
                            atomicAdd(&shist[(key >> 20) - PIVOT_BIN], 1u);
                            unsigned p = atomicAdd(&scnt, 1u);
                            sbuf[p] = make_uint2(key, gb + (unsigned)e);
                        }
                    }
                    ot[ii[j]] = z4;
                }
            }
            __syncthreads();
            unsigned cnt = scnt;                       // <= 4096 by construction
            if (cnt) {
                if (tid == 0) sbase = atomicAdd(&g_ncand, cnt);
                __syncthreads();
                for (unsigned k = tid; k < cnt; k += bd) {
                    unsigned p = sbase + k;
                    if (p < CAP) g_cand[p] = sbuf[k];
                }
            }
            __syncthreads();
        }
    }
    __syncthreads();
    for (int i = tid; i < 1024; i += bd) {
        unsigned vv = shist[i];
        if (vv) atomicAdd(&g_hist[PIVOT_BIN + i], vv);
    }
}

// ------------------------------------------------- K2: find boundary bin
__global__ void k2_findbin(unsigned ktot) {
    __shared__ unsigned part[1024];
    const int tid = threadIdx.x;
    unsigned nc = g_ncand;
    if (nc < ktot || nc > CAP) { if (tid == 0) g_flag = 1u; return; }

    unsigned h[4]; unsigned own = 0u;
#pragma unroll
    for (int j = 0; j < 4; j++) { h[j] = g_hist[tid * 4 + j]; own += h[j]; }
    part[tid] = own;
    __syncthreads();
    for (int off = 1; off < 1024; off <<= 1) {
        unsigned v = (tid + off < 1024) ? part[tid + off] : 0u;
        __syncthreads();
        part[tid] += v;
        __syncthreads();
    }
    unsigned above = part[tid] - own;
    unsigned cum = above;
    for (int j = 3; j >= 0; j--) {
        cum += h[j];
        if (cum >= ktot && (cum - h[j]) < ktot) {
            g_b1 = tid * 4 + j;
            g_need = ktot - (cum - h[j]);
        }
    }
}

// ------------------------------------ FB1: full histogram (fallback only)
__global__ void fb1_hist(const float* __restrict__ x,
                         const int* __restrict__ mask, int T, int F) {
    if (g_flag == 0u) return;
    __shared__ unsigned sh[NBIN];
    for (int b = threadIdx.x; b < NBIN; b += blockDim.x) sh[b] = 0u;
    __syncthreads();
    const int f4 = F >> 2;
    for (int t = blockIdx.x; t < T; t += gridDim.x) {
        if (mask[t] == 0) continue;
        const float4* xt = (const float4*)(x + (size_t)t * F);
        for (int i = threadIdx.x; i < f4; i += blockDim.x) {
            float4 v = xt[i];
            atomicAdd(&sh[f2key(__float_as_uint(v.x)) >> 20], 1u);
            atomicAdd(&sh[f2key(__float_as_uint(v.y)) >> 20], 1u);
            atomicAdd(&sh[f2key(__float_as_uint(v.z)) >> 20], 1u);
            atomicAdd(&sh[f2key(__float_as_uint(v.w)) >> 20], 1u);
        }
    }
    __syncthreads();
    for (int b = threadIdx.x; b < NBIN; b += blockDim.x) {
        unsigned v = sh[b];
        if (v) atomicAdd(&g_histF[b], v);
    }
}

// --------------------------------- FB2: re-find b1 from full histogram
__global__ void fb2_find(unsigned ktot) {
    if (g_flag == 0u) return;
    __shared__ unsigned part[1024];
    const int tid = threadIdx.x;
    unsigned h[4]; unsigned own = 0u;
#pragma unroll
    for (int j = 0; j < 4; j++) { h[j] = g_histF[tid * 4 + j]; own += h[j]; }
    part[tid] = own;
    __syncthreads();
    for (int off = 1; off < 1024; off <<= 1) {
        unsigned v = (tid + off < 1024) ? part[tid + off] : 0u;
        __syncthreads();
        part[tid] += v;
        __syncthreads();
    }
    unsigned above = part[tid] - own;
    unsigned cum = above;
    for (int j = 3; j >= 0; j--) {
        cum += h[j];
        if (cum >= ktot && (cum - h[j]) < ktot) {
            g_b1 = tid * 4 + j;
            g_need = ktot - (cum - h[j]);
        }
    }
    __syncthreads();
    if (tid == 0) {
        g_ncand = 0u;                        // FB3 recompacts
        if (part[0] < ktot) {                // fewer eligible than k: take all
            unsigned above0 = part[0] - g_histF[0];
            g_b1 = 0;
            g_need = ktot - above0;
        }
    }
}

// --------------------------- FB3: recompact bins >= b1 (fallback only)
// blockDim MUST be 256.
__global__ void fb3_compact(const float* __restrict__ x,
                            const int* __restrict__ mask, int T, int F) {
    if (g_flag == 0u) return;
    __shared__ uint2 sbuf[4096];
    __shared__ unsigned scnt, sbase;
    const int tid = threadIdx.x;
    const int bd = blockDim.x;
    const int f4 = F >> 2;
    const unsigned kmin = ((unsigned)g_b1) << 20;
    const int chunk = 4 * bd;
    const int nchunk = (f4 + chunk - 1) / chunk;
    const float4 z4 = make_float4(0.f, 0.f, 0.f, 0.f);

    for (int t = blockIdx.x; t < T; t += gridDim.x) {
        if (mask[t] == 0) continue;
        const float4* xt = (const float4*)(x + (size_t)t * F);
        const unsigned tbase = (unsigned)t * (unsigned)F;
        for (int c = 0; c < nchunk; c++) {
            if (tid == 0) scnt = 0u;
            __syncthreads();
            const int base = c * chunk;
            float4 v[4]; int ii[4]; bool act[4];
#pragma unroll
            for (int j = 0; j < 4; j++) {
                ii[j] = base + j * bd + tid;
                act[j] = ii[j] < f4;
                v[j] = act[j] ? xt[ii[j]] : z4;
            }
#pragma unroll
            for (int j = 0; j < 4; j++) {
                if (act[j]) {
                    const unsigned gb = tbase + ((unsigned)ii[j] << 2);
                    const float* vp = (const float*)&v[j];
#pragma unroll
                    for (int e = 0; e < 4; e++) {
                        unsigned key = f2key(__float_as_uint(vp[e]));
                        if (key >= kmin) {
                            unsigned p = atomicAdd(&scnt, 1u);
                            sbuf[p] = make_uint2(key, gb + (unsigned)e);
                        }
                    }
                }
            }
            __syncthreads();
            unsigned cnt = scnt;
            if (cnt) {
                if (tid == 0) sbase = atomicAdd(&g_ncand, cnt);
                __syncthreads();
                for (unsigned k = tid; k < cnt; k += bd) {
                    unsigned p = sbase + k;
                    if (p < CAP) g_cand[p] = sbuf[k];
                }
            }
            __syncthreads();
        }
    }
}

// ---------------- K4a: scatter definite winners, compact boundary bin
__global__ void k4a_split(float* __restrict__ out) {
    __shared__ unsigned sh2[256];
    __shared__ uint2 sbuf[512];
    __shared__ unsigned scnt, sbase, sminkey;
    const int tid = threadIdx.x;
    const int bd = blockDim.x;
    for (int i = tid; i < 256; i += bd) sh2[i] = 0u;
    if (tid == 0) sminkey = 0xFFFFFFFFu;
    __syncthreads();

    const int b1 = g_b1;
    const unsigned nc = min(g_ncand, CAP);
    const unsigned stride = (unsigned)bd * gridDim.x;
    unsigned lmin = 0xFFFFFFFFu;

    for (unsigned base = (unsigned)blockIdx.x * bd; base < nc; base += stride) {
        if (tid == 0) scnt = 0u;
        __syncthreads();
        unsigned i = base + tid;
        if (i < nc) {
            uint2 c = g_cand[i];
            int bin = (int)(c.x >> 20);
            if (bin > b1) {
                out[c.y] = fmaxf(key2f(c.x), 0.f);
                if (c.x > KEY_ZERO) lmin = min(lmin, c.x);
            } else if (bin == b1) {
                unsigned p = atomicAdd(&scnt, 1u);
                sbuf[p] = c;                           // p < bd <= 512
                atomicAdd(&sh2[(c.x >> 12) & 255u], 1u);
            }
        }
        __syncthreads();
        unsigned cnt = scnt;
        if (cnt) {
            if (tid == 0) sbase = atomicAdd(&g_ncand2, cnt);
            __syncthreads();
            for (unsigned k = tid; k < cnt; k += bd) {
                unsigned p = sbase + k;
                if (p < CAP2) g_cand2[p] = sbuf[k];
            }
        }
        __syncthreads();
    }
    atomicMin(&sminkey, lmin);
    __syncthreads();
    for (int i = tid; i < 256; i += bd) {
        unsigned v = sh2[i];
        if (v) atomicAdd(&g_h2[i], v);
    }
    if (tid == 0 && sminkey != 0xFFFFFFFFu) atomicMin(&g_minpos, sminkey);
}

// ------------- K4b: finish select in boundary bin, ties, EMA threshold
__global__ void k4b_final(const float* __restrict__ thr_in,
                          float* __restrict__ out, int n, int out_size) {
    __shared__ unsigned h[256];
    __shared__ unsigned s_sel, s_need, s_tiecnt, s_minpos;
    __shared__ unsigned tie_idx[MAXTIE];
    const int tid = threadIdx.x;
    const int bd = blockDim.x;
    const int b1 = g_b1;
    unsigned need = g_need;
    const unsigned nc2 = min(g_ncand2, CAP2);
    unsigned ck = 0u;
    bool have = (b1 >= 0) && need > 0u && nc2 > 0u;

    if (have) {
        if (tid == 0) {
            unsigned cum = 0u; s_sel = 0u; s_need = need;
            for (int d = 255; d >= 0; d--) {
                unsigned hv = g_h2[d];
                cum += hv;
                if (cum >= need) { s_sel = (unsigned)d; s_need = need - (cum - hv); break; }
            }
        }
        __syncthreads();
        unsigned prefix = ((unsigned)b1 << 20) | (s_sel << 12);
        unsigned pmask = 0xFFFFF000u;
        need = s_need;

        const int shifts[2] = {4, 0};
        const unsigned widths[2] = {256u, 16u};
#pragma unroll
        for (int lev = 0; lev < 2; lev++) {
            const int sh = shifts[lev];
            const unsigned w = widths[lev];
            for (unsigned d = tid; d < w; d += bd) h[d] = 0u;
            __syncthreads();
            for (unsigned i = tid; i < nc2; i += bd) {
                unsigned key = g_cand2[i].x;
                if ((key & pmask) == prefix) atomicAdd(&h[(key >> sh) & (w - 1u)], 1u);
            }
            __syncthreads();
            if (tid == 0) {
                unsigned cum = 0u; s_sel = 0u; s_need = need;
                for (int d = (int)w - 1; d >= 0; d--) {
                    cum += h[d];
                    if (cum >= need) { s_sel = (unsigned)d; s_need = need - (cum - h[d]); break; }
                }
            }
            __syncthreads();
            prefix |= s_sel << sh;
            pmask |= (w - 1u) << sh;
            need = s_need;
            __syncthreads();
        }
        ck = prefix;

        if (tid == 0) { s_tiecnt = 0u; s_minpos = 0xFFFFFFFFu; }
        __syncthreads();
        unsigned lmin = 0xFFFFFFFFu;
        for (unsigned i = tid; i < nc2; i += bd) {
            uint2 c = g_cand2[i];
            if (c.x > ck) {
                out[c.y] = fmaxf(key2f(c.x), 0.f);
                if (c.x > KEY_ZERO) lmin = min(lmin, c.x);
            } else if (c.x == ck) {
                unsigned p = atomicAdd(&s_tiecnt, 1u);
                if (p < MAXTIE) tie_idx[p] = c.y;
            }
        }
        atomicMin(&s_minpos, lmin);
        __syncthreads();
        unsigned tcnt = s_tiecnt;
        const float cv = fmaxf(key2f(ck), 0.f);
        if (tcnt <= (unsigned)MAXTIE) {
            for (unsigned i = tid; i < tcnt; i += bd) {
                unsigned mi = tie_idx[i];
                unsigned rank = 0u;
                for (unsigned j = 0; j < tcnt; j++) rank += (tie_idx[j] < mi) ? 1u : 0u;
                if (rank < need) out[mi] = cv;
            }
        } else {
            for (unsigned i = tid; i < need && i < (unsigned)MAXTIE; i += bd)
                out[tie_idx[i]] = cv;
        }
        __syncthreads();
    }

    if (tid == 0) {
        unsigned mp = g_minpos;
        if (have) {
            mp = min(mp, s_minpos);
            if (need > 0u && ck > KEY_ZERO) mp = min(mp, ck);
        }
        float thr = thr_in[0];
        float res = thr;
        if (mp != 0xFFFFFFFFu) res = 0.99f * thr + 0.01f * key2f(mp);
        out[out_size - 1] = res;
    }
}

// ---------------------------------------------------------------------------
extern "C" void kernel_launch(void* const* d_in, const int* in_sizes, int n_in,
                              void* d_out, int out_size) {
    const float* x = (const float*)d_in[0];
    const int* mask = (const int*)d_in[1];
    const float* thr = (const float*)d_in[2];
    float* out = (float*)d_out;

    const int n = in_sizes[0];
    const int T = in_sizes[1];
    const int F = n / T;
    const unsigned ktot = 32u * (unsigned)T;

    int gm = T < 2048 ? T : 2048;

    k0_init<<<1, 1024>>>();
    km_fused<<<gm, 256>>>(x, mask, out, T, F);
    k2_findbin<<<1, 1024>>>(ktot);
    fb1_hist<<<512, 256>>>(x, mask, T, F);
    fb2_find<<<1, 1024>>>(ktot);
    fb3_compact<<<512, 256>>>(x, mask, T, F);
    k4a_split<<<128, 256>>>(out);
    k4b_final<<<1, 1024>>>(thr, out, n, out_size);
}

// round 3
// speedup vs baseline: 1.2752x; 1.0773x over previous
#include <cuda_runtime.h>
#include <stdint.h>

// ---------------------------------------------------------------------------
// BatchTopK: global top-(32*T) over masked [B,S,F], scatter relu'd winners,
// EMA threshold. Pure-stream pipeline:
//   KZ  : zero full output (pure write stream) + init persistent state (blk 0)
//   KS  : read eligible x ONCE; warp-ballot compaction of keys >= pivot(2.25)
//         into per-warp smem buffers; 1023-bin histogram of candidate bins
//   K2  : suffix-scan hist -> boundary bin b1 + need (or set fallback flag)
//   FB1/FB2/FB3: exactness fallback (early-exit when flag==0)
//   K4a : split candidates: bin>b1 -> scatter winners; bin==b1 -> cand2 + h2
//   K4b : finish radix select in bin b1, ties by lowest index, EMA threshold
// ---------------------------------------------------------------------------

#define NBIN 4096
#define PIVOT_KEY 0xC0100000u   // f2key(2.25f)
#define PIVOT_BIN 3073          // PIVOT_KEY >> 20
#define NH (NBIN - PIVOT_BIN)   // 1023 hist bins
#define KEY_ZERO  0x80000000u   // f2key(+0.0f)
#define CAP  (1u << 22)
#define CAP2 (1u << 20)
#define MAXTIE 4096
#define WBUF_CAP 96
#define WBUF_FLUSH 64

__device__ unsigned g_hist[NBIN];
__device__ unsigned g_histF[NBIN];
__device__ unsigned g_h2[256];
__device__ int      g_b1;
__device__ unsigned g_need;
__device__ unsigned g_ncand;
__device__ unsigned g_ncand2;
__device__ unsigned g_flag;
__device__ unsigned g_minpos;
__device__ uint2    g_cand[CAP];
__device__ uint2    g_cand2[CAP2];

__device__ __forceinline__ unsigned f2key(unsigned u) {
    unsigned m = ((unsigned)((int)u >> 31)) | 0x80000000u;
    return u ^ m;
}
__device__ __forceinline__ float key2f(unsigned k) {
    unsigned u = (k & 0x80000000u) ? (k ^ 0x80000000u) : ~k;
    return __uint_as_float(u);
}

// ----------------------------------------- KZ: zero output + init state
__global__ void kz_zero(float* __restrict__ out, int out_size) {
    const int tid = blockIdx.x * blockDim.x + threadIdx.x;
    const int nt = blockDim.x * gridDim.x;
    if (blockIdx.x == 0) {   // piggyback state init
        for (int i = threadIdx.x; i < NBIN; i += blockDim.x) { g_hist[i] = 0u; g_histF[i] = 0u; }
        for (int i = threadIdx.x; i < 256; i += blockDim.x) g_h2[i] = 0u;
        if (threadIdx.x == 0) {
            g_b1 = -1; g_need = 0u; g_ncand = 0u; g_ncand2 = 0u;
            g_flag = 0u; g_minpos = 0xFFFFFFFFu;
        }
    }
    const int n4 = out_size >> 2;
    float4* o4 = (float4*)out;
    const float4 z = make_float4(0.f, 0.f, 0.f, 0.f);
    for (int i = tid; i < n4; i += nt) o4[i] = z;
    for (int i = (n4 << 2) + tid; i < out_size; i += nt) out[i] = 0.f;
}

// ------------------------------------------- KS: scan + compact candidates
// blockDim MUST be 256 (8 warps).
__global__ void ks_scan(const float* __restrict__ x,
                        const int* __restrict__ mask, int T, int F) {
    __shared__ unsigned shist[NH];
    __shared__ uint2 wbuf[8][WBUF_CAP];
    __shared__ unsigned wc[8];
    __shared__ unsigned gb;
    const int tid = threadIdx.x;
    const int lane = tid & 31;
    const int w = tid >> 5;
    for (int i = tid; i < NH; i += blockDim.x) shist[i] = 0u;
    __syncthreads();

    const int f4 = F >> 2;
    unsigned cnt = 0u;   // warp-uniform candidate count in wbuf[w]

#define KS_PUSH(VAL, GIDX, ACT) do {                                          \
    unsigned key = f2key(__float_as_uint(VAL));                               \
    bool is = (ACT) && (key >= PIVOT_KEY);                                    \
    unsigned bal = __ballot_sync(0xFFFFFFFFu, is);                            \
    if (bal) {                                                                \
        if (is) {                                                             \
            unsigned r = __popc(bal & ((1u << lane) - 1u));                   \
            wbuf[w][cnt + r] = make_uint2(key, (GIDX));                       \
            atomicAdd(&shist[(key >> 20) - PIVOT_BIN], 1u);                   \
        }                                                                     \
        cnt += (unsigned)__popc(bal);                                         \
        if (cnt >= WBUF_FLUSH) {                                              \
            unsigned base;                                                    \
            if (lane == 0) base = atomicAdd(&g_ncand, cnt);                   \
            base = __shfl_sync(0xFFFFFFFFu, base, 0);                         \
            for (unsigned q = lane; q < cnt; q += 32u) {                      \
                unsigned p = base + q;                                        \
                if (p < CAP) g_cand[p] = wbuf[w][q];                          \
            }                                                                 \
            cnt = 0u;                                                         \
        }                                                                     \
    }                                                                         \
} while (0)

    for (int t = blockIdx.x; t < T; t += gridDim.x) {
        if (mask[t] == 0) continue;
        const float4* xt = (const float4*)(x + (size_t)t * F);
        const unsigned tbase = (unsigned)t * (unsigned)F;
        // warp-contiguous slice of the token
        const int per = f4 >> 3;
        const int ws = w * per;
        const int we = (w == 7) ? f4 : ws + per;
        int i = ws;
        for (; i + 128 <= we; i += 128) {
            float4 v[4];
#pragma unroll
            for (int j = 0; j < 4; j++) v[j] = xt[i + j * 32 + lane];
#pragma unroll
            for (int j = 0; j < 4; j++) {
                const unsigned gb0 = tbase + (unsigned)((i + j * 32 + lane) << 2);
                KS_PUSH(v[j].x, gb0 + 0u, true);
                KS_PUSH(v[j].y, gb0 + 1u, true);
                KS_PUSH(v[j].z, gb0 + 2u, true);
                KS_PUSH(v[j].w, gb0 + 3u, true);
            }
        }
        for (; i < we; i += 32) {
            const int ii = i + lane;
            const bool a = ii < we;
            float4 v = a ? xt[ii] : make_float4(0.f, 0.f, 0.f, 0.f);
            const unsigned gb0 = tbase + (unsigned)(ii << 2);
            KS_PUSH(v.x, gb0 + 0u, a);
            KS_PUSH(v.y, gb0 + 1u, a);
            KS_PUSH(v.z, gb0 + 2u, a);
            KS_PUSH(v.w, gb0 + 3u, a);
        }
    }
#undef KS_PUSH

    // combined block flush: one global atomic for all 8 warp buffers
    if (lane == 0) wc[w] = cnt;
    __syncthreads();
    if (tid == 0) {
        unsigned s = 0;
        for (int q = 0; q < 8; q++) { unsigned c = wc[q]; wc[q] = s; s += c; }
        gb = s ? atomicAdd(&g_ncand, s) : 0u;
    }
    __syncthreads();
    {
        const unsigned base = gb + wc[w];
        for (unsigned q = lane; q < cnt; q += 32u) {
            unsigned p = base + q;
            if (p < CAP) g_cand[p] = wbuf[w][q];
        }
    }
    __syncthreads();
    for (int i = tid; i < NH; i += blockDim.x) {
        unsigned v = shist[i];
        if (v) atomicAdd(&g_hist[PIVOT_BIN + i], v);
    }
}

// ------------------------------------------------- K2: find boundary bin
__global__ void k2_findbin(unsigned ktot) {
    __shared__ unsigned part[1024];
    const int tid = threadIdx.x;
    unsigned nc = g_ncand;
    if (nc < ktot || nc > CAP) { if (tid == 0) g_flag = 1u; return; }

    unsigned own = (tid < NH) ? g_hist[PIVOT_BIN + tid] : 0u;
    part[tid] = own;
    __syncthreads();
    for (int off = 1; off < 1024; off <<= 1) {
        unsigned v = (tid + off < 1024) ? part[tid + off] : 0u;
        __syncthreads();
        part[tid] += v;
        __syncthreads();
    }
    unsigned above = part[tid] - own;    // strictly above this bin
    if (own && above < ktot && above + own >= ktot) {
        g_b1 = PIVOT_BIN + tid;
        g_need = ktot - above;
    }
}

// ------------------------------------ FB1: full histogram (fallback only)
__global__ void fb1_hist(const float* __restrict__ x,
                         const int* __restrict__ mask, int T, int F) {
    if (g_flag == 0u) return;
    __shared__ unsigned sh[NBIN];
    for (int b = threadIdx.x; b < NBIN; b += blockDim.x) sh[b] = 0u;
    __syncthreads();
    const int f4 = F >> 2;
    for (int t = blockIdx.x; t < T; t += gridDim.x) {
        if (mask[t] == 0) continue;
        const float4* xt = (const float4*)(x + (size_t)t * F);
        for (int i = threadIdx.x; i < f4; i += blockDim.x) {
            float4 v = xt[i];
            atomicAdd(&sh[f2key(__float_as_uint(v.x)) >> 20], 1u);
            atomicAdd(&sh[f2key(__float_as_uint(v.y)) >> 20], 1u);
            atomicAdd(&sh[f2key(__float_as_uint(v.z)) >> 20], 1u);
            atomicAdd(&sh[f2key(__float_as_uint(v.w)) >> 20], 1u);
        }
    }
    __syncthreads();
    for (int b = threadIdx.x; b < NBIN; b += blockDim.x) {
        unsigned v = sh[b];
        if (v) atomicAdd(&g_histF[b], v);
    }
}

// --------------------------------- FB2: re-find b1 from full histogram
__global__ void fb2_find(unsigned ktot) {
    if (g_flag == 0u) return;
    __shared__ unsigned part[1024];
    const int tid = threadIdx.x;
    unsigned h[4]; unsigned own = 0u;
#pragma unroll
    for (int j = 0; j < 4; j++) { h[j] = g_histF[tid * 4 + j]; own += h[j]; }
    part[tid] = own;
    __syncthreads();
    for (int off = 1; off < 1024; off <<= 1) {
        unsigned v = (tid + off < 1024) ? part[tid + off] : 0u;
        __syncthreads();
        part[tid] += v;
        __syncthreads();
    }
    unsigned above = part[tid] - own;
    unsigned cum = above;
    for (int j = 3; j >= 0; j--) {
        cum += h[j];
        if (cum >= ktot && (cum - h[j]) < ktot) {
            g_b1 = tid * 4 + j;
            g_need = ktot - (cum - h[j]);
        }
    }
    __syncthreads();
    if (tid == 0) {
        g_ncand = 0u;                        // FB3 recompacts
        if (part[0] < ktot) {                // fewer eligible than k: take all
            unsigned above0 = part[0] - g_histF[0];
            g_b1 = 0;
            g_need = ktot - above0;
        }
    }
}

// --------------------------- FB3: recompact bins >= b1 (fallback only)
// blockDim MUST be 256.
__global__ void fb3_compact(const float* __restrict__ x,
                            const int* __restrict__ mask, int T, int F) {
    if (g_flag == 0u) return;
    __shared__ uint2 sbuf[4096];
    __shared__ unsigned scnt, sbase;
    const int tid = threadIdx.x;
    const int bd = blockDim.x;
    const int f4 = F >> 2;
    const unsigned kmin = ((unsigned)g_b1) << 20;
    const int chunk = 4 * bd;
    const int nchunk = (f4 + chunk - 1) / chunk;
    const float4 z4 = make_float4(0.f, 0.f, 0.f, 0.f);

    for (int t = blockIdx.x; t < T; t += gridDim.x) {
        if (mask[t] == 0) continue;
        const float4* xt = (const float4*)(x + (size_t)t * F);
        const unsigned tbase = (unsigned)t * (unsigned)F;
        for (int c = 0; c < nchunk; c++) {
            if (tid == 0) scnt = 0u;
            __syncthreads();
            const int base = c * chunk;
            float4 v[4]; int ii[4]; bool act[4];
#pragma unroll
            for (int j = 0; j < 4; j++) {
                ii[j] = base + j * bd + tid;
                act[j] = ii[j] < f4;
                v[j] = act[j] ? xt[ii[j]] : z4;
            }
#pragma unroll
            for (int j = 0; j < 4; j++) {
                if (act[j]) {
                    const unsigned gb0 = tbase + ((unsigned)ii[j] << 2);
                    const float* vp = (const float*)&v[j];
#pragma unroll
                    for (int e = 0; e < 4; e++) {
                        unsigned key = f2key(__float_as_uint(vp[e]));
                        if (key >= kmin) {
                            unsigned p = atomicAdd(&scnt, 1u);
                            sbuf[p] = make_uint2(key, gb0 + (unsigned)e);
                        }
                    }
                }
            }
            __syncthreads();
            unsigned cnt = scnt;
            if (cnt) {
                if (tid == 0) sbase = atomicAdd(&g_ncand, cnt);
                __syncthreads();
                for (unsigned k = tid; k < cnt; k += bd) {
                    unsigned p = sbase + k;
                    if (p < CAP) g_cand[p] = sbuf[k];
                }
            }
            __syncthreads();
        }
    }
}

// ---------------- K4a: scatter definite winners, compact boundary bin
__global__ void k4a_split(float* __restrict__ out) {
    __shared__ unsigned sh2[256];
    __shared__ uint2 sbuf[512];
    __shared__ unsigned scnt, sbase, sminkey;
    const int tid = threadIdx.x;
    const int bd = blockDim.x;
    for (int i = tid; i < 256; i += bd) sh2[i] = 0u;
    if (tid == 0) sminkey = 0xFFFFFFFFu;
    __syncthreads();

    const int b1 = g_b1;
    const unsigned nc = min(g_ncand, CAP);
    const unsigned stride = (unsigned)bd * gridDim.x;
    unsigned lmin = 0xFFFFFFFFu;

    for (unsigned base = (unsigned)blockIdx.x * bd; base < nc; base += stride) {
        if (tid == 0) scnt = 0u;
        __syncthreads();
        unsigned i = base + tid;
        if (i < nc) {
            uint2 c = g_cand[i];
            int bin = (int)(c.x >> 20);
            if (bin > b1) {
                out[c.y] = fmaxf(key2f(c.x), 0.f);
                if (c.x > KEY_ZERO) lmin = min(lmin, c.x);
            } else if (bin == b1) {
                unsigned p = atomicAdd(&scnt, 1u);
                sbuf[p] = c;
                atomicAdd(&sh2[(c.x >> 12) & 255u], 1u);
            }
        }
        __syncthreads();
        unsigned cnt = scnt;
        if (cnt) {
            if (tid == 0) sbase = atomicAdd(&g_ncand2, cnt);
            __syncthreads();
            for (unsigned k = tid; k < cnt; k += bd) {
                unsigned p = sbase + k;
                if (p < CAP2) g_cand2[p] = sbuf[k];
            }
        }
        __syncthreads();
    }
    atomicMin(&sminkey, lmin);
    __syncthreads();
    for (int i = tid; i < 256; i += bd) {
        unsigned v = sh2[i];
        if (v) atomicAdd(&g_h2[i], v);
    }
    if (tid == 0 && sminkey != 0xFFFFFFFFu) atomicMin(&g_minpos, sminkey);
}

// ------------- K4b: finish select in boundary bin, ties, EMA threshold
__global__ void k4b_final(const float* __restrict__ thr_in,
                          float* __restrict__ out, int n, int out_size) {
    __shared__ unsigned h[256];
    __shared__ unsigned s_sel, s_need, s_tiecnt, s_minpos;
    __shared__ unsigned tie_idx[MAXTIE];
    const int tid = threadIdx.x;
    const int bd = blockDim.x;
    const int b1 = g_b1;
    unsigned need = g_need;
    const unsigned nc2 = min(g_ncand2, CAP2);
    unsigned ck = 0u;
    bool have = (b1 >= 0) && need > 0u && nc2 > 0u;

    if (have) {
        if (tid == 0) {
            unsigned cum = 0u; s_sel = 0u; s_need = need;
            for (int d = 255; d >= 0; d--) {
                unsigned hv = g_h2[d];
                cum += hv;
                if (cum >= need) { s_sel = (unsigned)d; s_need = need - (cum - hv); break; }
            }
        }
        __syncthreads();
        unsigned prefix = ((unsigned)b1 << 20) | (s_sel << 12);
        unsigned pmask = 0xFFFFF000u;
        need = s_need;

        const int shifts[2] = {4, 0};
        const unsigned widths[2] = {256u, 16u};
#pragma unroll
        for (int lev = 0; lev < 2; lev++) {
            const int sh = shifts[lev];
            const unsigned w = widths[lev];
            for (unsigned d = tid; d < w; d += bd) h[d] = 0u;
            __syncthreads();
            for (unsigned i = tid; i < nc2; i += bd) {
                unsigned key = g_cand2[i].x;
                if ((key & pmask) == prefix) atomicAdd(&h[(key >> sh) & (w - 1u)], 1u);
            }
            __syncthreads();
            if (tid == 0) {
                unsigned cum = 0u; s_sel = 0u; s_need = need;
                for (int d = (int)w - 1; d >= 0; d--) {
                    cum += h[d];
                    if (cum >= need) { s_sel = (unsigned)d; s_need = need - (cum - h[d]); break; }
                }
            }
            __syncthreads();
            prefix |= s_sel << sh;
            pmask |= (w - 1u) << sh;
            need = s_need;
            __syncthreads();
        }
        ck = prefix;

        if (tid == 0) { s_tiecnt = 0u; s_minpos = 0xFFFFFFFFu; }
        __syncthreads();
        unsigned lmin = 0xFFFFFFFFu;
        for (unsigned i = tid; i < nc2; i += bd) {
            uint2 c = g_cand2[i];
            if (c.x > ck) {
                out[c.y] = fmaxf(key2f(c.x), 0.f);
                if (c.x > KEY_ZERO) lmin = min(lmin, c.x);
            } else if (c.x == ck) {
                unsigned p = atomicAdd(&s_tiecnt, 1u);
                if (p < MAXTIE) tie_idx[p] = c.y;
            }
        }
        atomicMin(&s_minpos, lmin);
        __syncthreads();
        unsigned tcnt = s_tiecnt;
        const float cv = fmaxf(key2f(ck), 0.f);
        if (tcnt <= (unsigned)MAXTIE) {
            for (unsigned i = tid; i < tcnt; i += bd) {
                unsigned mi = tie_idx[i];
                unsigned rank = 0u;
                for (unsigned j = 0; j < tcnt; j++) rank += (tie_idx[j] < mi) ? 1u : 0u;
                if (rank < need) out[mi] = cv;
            }
        } else {
            for (unsigned i = tid; i < need && i < (unsigned)MAXTIE; i += bd)
                out[tie_idx[i]] = cv;
        }
        __syncthreads();
    }

    if (tid == 0) {
        unsigned mp = g_minpos;
        if (have) {
            mp = min(mp, s_minpos);
            if (need > 0u && ck > KEY_ZERO) mp = min(mp, ck);
        }
        float thr = thr_in[0];
        float res = thr;
        if (mp != 0xFFFFFFFFu) res = 0.99f * thr + 0.01f * key2f(mp);
        out[out_size - 1] = res;
    }
}

// ---------------------------------------------------------------------------
extern "C" void kernel_launch(void* const* d_in, const int* in_sizes, int n_in,
                              void* d_out, int out_size) {
    const float* x = (const float*)d_in[0];
    const int* mask = (const int*)d_in[1];
    const float* thr = (const float*)d_in[2];
    float* out = (float*)d_out;

    const int n = in_sizes[0];
    const int T = in_sizes[1];
    const int F = n / T;
    const unsigned ktot = 32u * (unsigned)T;

    int gs = T < 2048 ? T : 2048;

    kz_zero<<<2048, 256>>>(out, out_size);
    ks_scan<<<gs, 256>>>(x, mask, T, F);
    k2_findbin<<<1, 1024>>>(ktot);
    fb1_hist<<<256, 256>>>(x, mask, T, F);
    fb2_find<<<1, 1024>>>(ktot);
    fb3_compact<<<256, 256>>>(x, mask, T, F);
    k4a_split<<<128, 256>>>(out);
    k4b_final<<<1, 1024>>>(thr, out, n, out_size);
}

// round 4
// speedup vs baseline: 1.3806x; 1.0826x over previous
#include <cuda_runtime.h>
#include <stdint.h>

// ---------------------------------------------------------------------------
// BatchTopK: global top-(32*T) over masked [B,S,F], scatter relu'd winners,
// EMA threshold. 5-launch pipeline:
//   KMS : fused stream — zero output, read eligible x once, warp-ballot
//         compaction of keys >= pivot(2.25) + 1023-bin histogram
//   K2  : suffix-scan hist -> boundary bin b1 + need (or set fallback flag)
//   FB  : single-block exact fallback (dormant: reads one flag, exits)
//   K4a : split candidates: bin>b1 -> scatter winners; bin==b1 -> cand2 + h2
//   K4b : finish radix select in bin b1, ties by lowest index, EMA threshold,
//         then RESET all persistent state for the next graph replay
// State is statically zero-initialized (first run) and reset by K4b (replays).
// ---------------------------------------------------------------------------

#define NBIN 4096
#define PIVOT_KEY 0xC0100000u   // f2key(2.25f)
#define PIVOT_BIN 3073          // PIVOT_KEY >> 20
#define NH (NBIN - PIVOT_BIN)   // 1023 hist bins
#define KEY_ZERO  0x80000000u   // f2key(+0.0f)
#define CAP  (1u << 22)
#define CAP2 (1u << 20)
#define MAXTIE 4096
#define WBUF_CAP 96
#define WBUF_FLUSH 64

__device__ unsigned g_hist[NBIN];
__device__ unsigned g_h2[256];
__device__ int      g_b1 = -1;
__device__ unsigned g_need;
__device__ unsigned g_ncand;
__device__ unsigned g_ncand2;
__device__ unsigned g_flag;
__device__ unsigned g_minpos = 0xFFFFFFFFu;
__device__ uint2    g_cand[CAP];
__device__ uint2    g_cand2[CAP2];

__device__ __forceinline__ unsigned f2key(unsigned u) {
    unsigned m = ((unsigned)((int)u >> 31)) | 0x80000000u;
    return u ^ m;
}
__device__ __forceinline__ float key2f(unsigned k) {
    unsigned u = (k & 0x80000000u) ? (k ^ 0x80000000u) : ~k;
    return __uint_as_float(u);
}

// ------------------------- KMS: fused zero + scan + compact + histogram
// blockDim MUST be 256 (8 warps).
__global__ void kms_stream(const float* __restrict__ x,
                           const int* __restrict__ mask,
                           float* __restrict__ out, int T, int F) {
    __shared__ unsigned shist[NH];
    __shared__ uint2 wbuf[8][WBUF_CAP];
    __shared__ unsigned wc[8];
    __shared__ unsigned gbs;
    const int tid = threadIdx.x;
    const int lane = tid & 31;
    const int w = tid >> 5;
    for (int i = tid; i < NH; i += blockDim.x) shist[i] = 0u;
    __syncthreads();

    const int f4 = F >> 2;
    const float4 z4 = make_float4(0.f, 0.f, 0.f, 0.f);
    unsigned cnt = 0u;   // warp-uniform count in wbuf[w]

#define KS_PUSH(VAL, GIDX, ACT) do {                                          \
    unsigned key = f2key(__float_as_uint(VAL));                               \
    bool is = (ACT) && (key >= PIVOT_KEY);                                    \
    unsigned bal = __ballot_sync(0xFFFFFFFFu, is);                            \
    if (bal) {                                                                \
        if (is) {                                                             \
            unsigned r = __popc(bal & ((1u << lane) - 1u));                   \
            wbuf[w][cnt + r] = make_uint2(key, (GIDX));                       \
            atomicAdd(&shist[(key >> 20) - PIVOT_BIN], 1u);                   \
        }                                                                     \
        cnt += (unsigned)__popc(bal);                                         \
        if (cnt >= WBUF_FLUSH) {                                              \
            unsigned base;                                                    \
            if (lane == 0) base = atomicAdd(&g_ncand, cnt);                   \
            base = __shfl_sync(0xFFFFFFFFu, base, 0);                         \
            for (unsigned q = lane; q < cnt; q += 32u) {                      \
                unsigned p = base + q;                                        \
                if (p < CAP) g_cand[p] = wbuf[w][q];                          \
            }                                                                 \
            cnt = 0u;                                                         \
        }                                                                     \
    }                                                                         \
} while (0)

    for (int t = blockIdx.x; t < T; t += gridDim.x) {
        float4* ot = (float4*)(out + (size_t)t * F);
        const int per = f4 >> 3;
        const int ws = w * per;
        const int we = (w == 7) ? f4 : ws + per;
        if (mask[t] == 0) {                      // masked: pure write stream
            for (int i = ws + lane; i < we; i += 32) ot[i] = z4;
            continue;
        }
        const float4* xt = (const float4*)(x + (size_t)t * F);
        const unsigned tbase = (unsigned)t * (unsigned)F;
        int i = ws;
        for (; i + 128 <= we; i += 128) {
            float4 v[4];
#pragma unroll
            for (int j = 0; j < 4; j++) v[j] = xt[i + j * 32 + lane];
#pragma unroll
            for (int j = 0; j < 4; j++) ot[i + j * 32 + lane] = z4;
#pragma unroll
            for (int j = 0; j < 4; j++) {
                const unsigned gb0 = tbase + (unsigned)((i + j * 32 + lane) << 2);
                KS_PUSH(v[j].x, gb0 + 0u, true);
                KS_PUSH(v[j].y, gb0 + 1u, true);
                KS_PUSH(v[j].z, gb0 + 2u, true);
                KS_PUSH(v[j].w, gb0 + 3u, true);
            }
        }
        for (; i < we; i += 32) {
            const int ii = i + lane;
            const bool a = ii < we;
            float4 v = a ? xt[ii] : z4;
            if (a) ot[ii] = z4;
            const unsigned gb0 = tbase + (unsigned)(ii << 2);
            KS_PUSH(v.x, gb0 + 0u, a);
            KS_PUSH(v.y, gb0 + 1u, a);
            KS_PUSH(v.z, gb0 + 2u, a);
            KS_PUSH(v.w, gb0 + 3u, a);
        }
    }
#undef KS_PUSH

    // combined block flush: one global atomic for all 8 warp buffers
    if (lane == 0) wc[w] = cnt;
    __syncthreads();
    if (tid == 0) {
        unsigned s = 0;
        for (int q = 0; q < 8; q++) { unsigned c = wc[q]; wc[q] = s; s += c; }
        gbs = s ? atomicAdd(&g_ncand, s) : 0u;
    }
    __syncthreads();
    {
        const unsigned base = gbs + wc[w];
        for (unsigned q = lane; q < cnt; q += 32u) {
            unsigned p = base + q;
            if (p < CAP) g_cand[p] = wbuf[w][q];
        }
    }
    __syncthreads();
    for (int i = tid; i < NH; i += blockDim.x) {
        unsigned v = shist[i];
        if (v) atomicAdd(&g_hist[PIVOT_BIN + i], v);
    }
}

// ------------------------------------------------- K2: find boundary bin
__global__ void k2_findbin(unsigned ktot) {
    __shared__ unsigned part[1024];
    const int tid = threadIdx.x;
    unsigned nc = g_ncand;
    if (nc < ktot || nc > CAP) { if (tid == 0) g_flag = 1u; return; }

    unsigned own = (tid < NH) ? g_hist[PIVOT_BIN + tid] : 0u;
    part[tid] = own;
    __syncthreads();
    for (int off = 1; off < 1024; off <<= 1) {
        unsigned v = (tid + off < 1024) ? part[tid + off] : 0u;
        __syncthreads();
        part[tid] += v;
        __syncthreads();
    }
    unsigned above = part[tid] - own;    // strictly above this bin
    if (own && above < ktot && above + own >= ktot) {
        g_b1 = PIVOT_BIN + tid;
        g_need = ktot - above;
    }
}

// ----------------- FB: single-block exact fallback (dormant: ~free)
__global__ void fb_all(const float* __restrict__ x,
                       const int* __restrict__ mask, int T, int F,
                       unsigned ktot) {
    if (g_flag == 0u) return;           // dormant path: one load, exit
    __shared__ unsigned sh[NBIN];
    __shared__ int s_b1;
    const int tid = threadIdx.x;
    const int bd = blockDim.x;
    for (int i = tid; i < NBIN; i += bd) sh[i] = 0u;
    __syncthreads();
    const int f4 = F >> 2;
    for (int t = 0; t < T; t++) {
        if (mask[t] == 0) continue;
        const float4* xt = (const float4*)(x + (size_t)t * F);
        for (int i = tid; i < f4; i += bd) {
            float4 v = xt[i];
            atomicAdd(&sh[f2key(__float_as_uint(v.x)) >> 20], 1u);
            atomicAdd(&sh[f2key(__float_as_uint(v.y)) >> 20], 1u);
            atomicAdd(&sh[f2key(__float_as_uint(v.z)) >> 20], 1u);
            atomicAdd(&sh[f2key(__float_as_uint(v.w)) >> 20], 1u);
        }
    }
    __syncthreads();
    if (tid == 0) {
        unsigned cum = 0u; int b1 = -1; unsigned need = 0u;
        for (int d = NBIN - 1; d >= 0; d--) {
            cum += sh[d];
            if (cum >= ktot) { b1 = d; need = ktot - (cum - sh[d]); break; }
        }
        if (b1 < 0) { b1 = 0; need = sh[0]; }   // fewer eligible than k: take all
        s_b1 = b1;
        g_b1 = b1; g_need = need; g_ncand = 0u;
    }
    __syncthreads();
    const unsigned kmin = ((unsigned)s_b1) << 20;
    for (int t = 0; t < T; t++) {
        if (mask[t] == 0) continue;
        const float4* xt = (const float4*)(x + (size_t)t * F);
        const unsigned tbase = (unsigned)t * (unsigned)F;
        for (int i = tid; i < f4; i += bd) {
            float4 v = xt[i];
            const unsigned gb0 = tbase + ((unsigned)i << 2);
            const float* vp = (const float*)&v;
#pragma unroll
            for (int e = 0; e < 4; e++) {
                unsigned key = f2key(__float_as_uint(vp[e]));
                if (key >= kmin) {
                    unsigned p = atomicAdd(&g_ncand, 1u);
                    if (p < CAP) g_cand[p] = make_uint2(key, gb0 + (unsigned)e);
                }
            }
        }
    }
}

// ---------------- K4a: scatter definite winners, compact boundary bin
__global__ void k4a_split(float* __restrict__ out) {
    __shared__ unsigned sh2[256];
    __shared__ uint2 sbuf[512];
    __shared__ unsigned scnt, sbase, sminkey;
    const int tid = threadIdx.x;
    const int bd = blockDim.x;
    for (int i = tid; i < 256; i += bd) sh2[i] = 0u;
    if (tid == 0) sminkey = 0xFFFFFFFFu;
    __syncthreads();

    const int b1 = g_b1;
    const unsigned nc = min(g_ncand, CAP);
    const unsigned stride = (unsigned)bd * gridDim.x;
    unsigned lmin = 0xFFFFFFFFu;

    for (unsigned base = (unsigned)blockIdx.x * bd; base < nc; base += stride) {
        if (tid == 0) scnt = 0u;
        __syncthreads();
        unsigned i = base + tid;
        if (i < nc) {
            uint2 c = g_cand[i];
            int bin = (int)(c.x >> 20);
            if (bin > b1) {
                out[c.y] = fmaxf(key2f(c.x), 0.f);
                if (c.x > KEY_ZERO) lmin = min(lmin, c.x);
            } else if (bin == b1) {
                unsigned p = atomicAdd(&scnt, 1u);
                sbuf[p] = c;
                atomicAdd(&sh2[(c.x >> 12) & 255u], 1u);
            }
        }
        __syncthreads();
        unsigned cnt = scnt;
        if (cnt) {
            if (tid == 0) sbase = atomicAdd(&g_ncand2, cnt);
            __syncthreads();
            for (unsigned k = tid; k < cnt; k += bd) {
                unsigned p = sbase + k;
                if (p < CAP2) g_cand2[p] = sbuf[k];
            }
        }
        __syncthreads();
    }
    atomicMin(&sminkey, lmin);
    __syncthreads();
    for (int i = tid; i < 256; i += bd) {
        unsigned v = sh2[i];
        if (v) atomicAdd(&g_h2[i], v);
    }
    if (tid == 0 && sminkey != 0xFFFFFFFFu) atomicMin(&g_minpos, sminkey);
}

// ------ K4b: finish select in bin b1, ties, EMA threshold, state reset
__global__ void k4b_final(const float* __restrict__ thr_in,
                          float* __restrict__ out, int n, int out_size) {
    __shared__ unsigned h[256];
    __shared__ unsigned s_sel, s_need, s_tiecnt, s_minpos;
    __shared__ unsigned tie_idx[MAXTIE];
    const int tid = threadIdx.x;
    const int bd = blockDim.x;
    const int b1 = g_b1;
    unsigned need = g_need;
    const unsigned nc2 = min(g_ncand2, CAP2);
    unsigned ck = 0u;
    bool have = (b1 >= 0) && need > 0u && nc2 > 0u;

    if (have) {
        if (tid == 0) {
            unsigned cum = 0u; s_sel = 0u; s_need = need;
            for (int d = 255; d >= 0; d--) {
                unsigned hv = g_h2[d];
                cum += hv;
                if (cum >= need) { s_sel = (unsigned)d; s_need = need - (cum - hv); break; }
            }
        }
        __syncthreads();
        unsigned prefix = ((unsigned)b1 << 20) | (s_sel << 12);
        unsigned pmask = 0xFFFFF000u;
        need = s_need;

        const int shifts[2] = {4, 0};
        const unsigned widths[2] = {256u, 16u};
#pragma unroll
        for (int lev = 0; lev < 2; lev++) {
            const int sh = shifts[lev];
            const unsigned w = widths[lev];
            for (unsigned d = tid; d < w; d += bd) h[d] = 0u;
            __syncthreads();
            for (unsigned i = tid; i < nc2; i += bd) {
                unsigned key = g_cand2[i].x;
                if ((key & pmask) == prefix) atomicAdd(&h[(key >> sh) & (w - 1u)], 1u);
            }
            __syncthreads();
            if (tid == 0) {
                unsigned cum = 0u; s_sel = 0u; s_need = need;
                for (int d = (int)w - 1; d >= 0; d--) {
                    cum += h[d];
                    if (cum >= need) { s_sel = (unsigned)d; s_need = need - (cum - h[d]); break; }
                }
            }
            __syncthreads();
            prefix |= s_sel << sh;
            pmask |= (w - 1u) << sh;
            need = s_need;
            __syncthreads();
        }
        ck = prefix;

        if (tid == 0) { s_tiecnt = 0u; s_minpos = 0xFFFFFFFFu; }
        __syncthreads();
        unsigned lmin = 0xFFFFFFFFu;
        for (unsigned i = tid; i < nc2; i += bd) {
            uint2 c = g_cand2[i];
            if (c.x > ck) {
                out[c.y] = fmaxf(key2f(c.x), 0.f);
                if (c.x > KEY_ZERO) lmin = min(lmin, c.x);
            } else if (c.x == ck) {
                unsigned p = atomicAdd(&s_tiecnt, 1u);
                if (p < MAXTIE) tie_idx[p] = c.y;
            }
        }
        atomicMin(&s_minpos, lmin);
        __syncthreads();
        unsigned tcnt = s_tiecnt;
        const float cv = fmaxf(key2f(ck), 0.f);
        if (tcnt <= (unsigned)MAXTIE) {
            for (unsigned i = tid; i < tcnt; i += bd) {
                unsigned mi = tie_idx[i];
                unsigned rank = 0u;
                for (unsigned j = 0; j < tcnt; j++) rank += (tie_idx[j] < mi) ? 1u : 0u;
                if (rank < need) out[mi] = cv;
            }
        } else {
            for (unsigned i = tid; i < need && i < (unsigned)MAXTIE; i += bd)
                out[tie_idx[i]] = cv;
        }
        __syncthreads();
    }

    if (tid == 0) {
        unsigned mp = g_minpos;
        if (have) {
            mp = min(mp, s_minpos);
            if (need > 0u && ck > KEY_ZERO) mp = min(mp, ck);
        }
        float thr = thr_in[0];
        float res = thr;
        if (mp != 0xFFFFFFFFu) res = 0.99f * thr + 0.01f * key2f(mp);
        out[out_size - 1] = res;
    }
    // zero any slack between data and threshold slot (harness poisons d_out)
    for (int i = n + tid; i < out_size - 1; i += bd) out[i] = 0.f;

    // ------------- reset persistent state for next graph replay -------------
    __syncthreads();
    for (int i = tid; i < NBIN; i += bd) g_hist[i] = 0u;
    for (int i = tid; i < 256; i += bd) g_h2[i] = 0u;
    if (tid == 0) {
        g_b1 = -1; g_need = 0u; g_ncand = 0u; g_ncand2 = 0u;
        g_flag = 0u; g_minpos = 0xFFFFFFFFu;
    }
}

// ---------------------------------------------------------------------------
extern "C" void kernel_launch(void* const* d_in, const int* in_sizes, int n_in,
                              void* d_out, int out_size) {
    const float* x = (const float*)d_in[0];
    const int* mask = (const int*)d_in[1];
    const float* thr = (const float*)d_in[2];
    float* out = (float*)d_out;

    const int n = in_sizes[0];
    const int T = in_sizes[1];
    const int F = n / T;
    const unsigned ktot = 32u * (unsigned)T;

    int gs = T < 2048 ? T : 2048;

    kms_stream<<<gs, 256>>>(x, mask, out, T, F);
    k2_findbin<<<1, 1024>>>(ktot);
    fb_all<<<1, 1024>>>(x, mask, T, F, ktot);
    k4a_split<<<128, 256>>>(out);
    k4b_final<<<1, 1024>>>(thr, out, n, out_size);
}